// round 1
// baseline (speedup 1.0000x reference)
#include <cuda_runtime.h>

// Shapes (fixed for this problem)
#define B_ 128
#define C_ 1024
#define D_ 256                   // = T (timesteps) = hidden dim
#define ROWS (B_*C_)             // 131072 rows for mix branch
#define CB (C_*B_)               // 131072
#define OB (D_*B_)               // 32768

// ---------------- scratch (static __device__, no allocation) ----------------
__device__ float g_xn[ROWS*D_];          // layernormed x          128 MB
__device__ float g_h [ROWS*D_];          // mix hidden             128 MB
__device__ float g_s1[D_*C_*B_];         // spikes 1 [t,c,b]       128 MB
__device__ float g_y1[D_*D_*B_];         // gemm1 out [t,o,b]       33 MB
__device__ float g_s2[D_*D_*B_];         // spikes 2 [t,o,b]        33 MB
__device__ float g_y2[D_*C_*B_];         // gemm2 out [t,c,b]      128 MB
__device__ float g_mu1[D_], g_rs1[D_];
__device__ float g_mu2[C_], g_rs2[C_];

// ---------------- packed f32x2 FMA helpers (sm_103a FFMA2) ----------------
__device__ __forceinline__ unsigned long long pk2(float x, float y) {
    unsigned long long r;
    asm("mov.b64 %0, {%1, %2};" : "=l"(r) : "f"(x), "f"(y));
    return r;
}
__device__ __forceinline__ void fma2(unsigned long long &d, unsigned long long a,
                                     unsigned long long b) {
    asm("fma.rn.f32x2 %0, %1, %2, %0;" : "+l"(d) : "l"(a), "l"(b));
}
__device__ __forceinline__ void up2(unsigned long long v, float &a, float &b) {
    asm("mov.b64 {%0, %1}, %2;" : "=f"(a), "=f"(b) : "l"(v));
}

// ---------------- 1) LayerNorm over last dim (D=256), 1 warp/row ----------------
__global__ void ln_kernel(const float* __restrict__ x, const float* __restrict__ gam,
                          const float* __restrict__ bet) {
    int gw = (blockIdx.x * blockDim.x + threadIdx.x) >> 5;
    int lane = threadIdx.x & 31;
    if (gw >= ROWS) return;
    const float4* xr = (const float4*)(x + (size_t)gw * D_);
    float4 v0 = xr[lane];
    float4 v1 = xr[lane + 32];
    float s = v0.x + v0.y + v0.z + v0.w + v1.x + v1.y + v1.z + v1.w;
    float q = v0.x*v0.x + v0.y*v0.y + v0.z*v0.z + v0.w*v0.w
            + v1.x*v1.x + v1.y*v1.y + v1.z*v1.z + v1.w*v1.w;
    #pragma unroll
    for (int o = 16; o; o >>= 1) {
        s += __shfl_xor_sync(0xffffffffu, s, o);
        q += __shfl_xor_sync(0xffffffffu, q, o);
    }
    float mu = s * (1.0f / D_);
    float var = q * (1.0f / D_) - mu * mu;
    float rs = rsqrtf(var + 1e-5f);
    const float4* gg = (const float4*)gam;
    const float4* bb = (const float4*)bet;
    float4 g0 = gg[lane], g1 = gg[lane + 32];
    float4 b0 = bb[lane], b1 = bb[lane + 32];
    float4 o0, o1;
    o0.x = (v0.x - mu) * rs * g0.x + b0.x;
    o0.y = (v0.y - mu) * rs * g0.y + b0.y;
    o0.z = (v0.z - mu) * rs * g0.z + b0.z;
    o0.w = (v0.w - mu) * rs * g0.w + b0.w;
    o1.x = (v1.x - mu) * rs * g1.x + b1.x;
    o1.y = (v1.y - mu) * rs * g1.y + b1.y;
    o1.z = (v1.z - mu) * rs * g1.z + b1.z;
    o1.w = (v1.w - mu) * rs * g1.w + b1.w;
    float4* xo = (float4*)(g_xn + (size_t)gw * D_);
    xo[lane] = o0;
    xo[lane + 32] = o1;
}

// ---------------- 2/3) Mix-branch GEMM: C[m,n] = epi(sum_k A[m,k]*W[n,k]) ----------------
// BM=BN=128, BK=16, 256 threads, 8x8 microtile via FFMA2.
// EPI=0: A=g_xn, out=g_h, epi = relu(acc + bias[n])
// EPI=1: A=g_h,  out=Cout, epi = X[m,n] + acc + bias[n]
template <int EPI>
__global__ void __launch_bounds__(256) gemm_mix(const float* __restrict__ W,
                                                const float* __restrict__ bias,
                                                const float* __restrict__ X,
                                                float* __restrict__ Cout) {
    __shared__ float As[16][132];
    __shared__ float Bs[16][132];
    const float* A = (EPI == 0) ? g_xn : g_h;
    float* Cw = (EPI == 0) ? g_h : Cout;
    int m0 = blockIdx.x * 128;
    int n0 = blockIdx.y * 128;
    int tid = threadIdx.x;
    int tx = tid & 15, ty = tid >> 4;
    unsigned long long acc[8][4] = {};
    int lr = tid >> 2;
    int lk = (tid & 3) << 2;
    for (int k0 = 0; k0 < 256; k0 += 16) {
        #pragma unroll
        for (int p = 0; p < 2; p++) {
            float4 av = *(const float4*)(A + (size_t)(m0 + lr + p * 64) * 256 + k0 + lk);
            As[lk + 0][lr + p * 64] = av.x;
            As[lk + 1][lr + p * 64] = av.y;
            As[lk + 2][lr + p * 64] = av.z;
            As[lk + 3][lr + p * 64] = av.w;
            float4 wv = *(const float4*)(W + (size_t)(n0 + lr + p * 64) * 256 + k0 + lk);
            Bs[lk + 0][lr + p * 64] = wv.x;
            Bs[lk + 1][lr + p * 64] = wv.y;
            Bs[lk + 2][lr + p * 64] = wv.z;
            Bs[lk + 3][lr + p * 64] = wv.w;
        }
        __syncthreads();
        #pragma unroll
        for (int k = 0; k < 16; k++) {
            float a[8];
            *(float4*)(a)     = *(const float4*)&As[k][ty * 8];
            *(float4*)(a + 4) = *(const float4*)&As[k][ty * 8 + 4];
            unsigned long long bp[4];
            #pragma unroll
            for (int j = 0; j < 4; j++)
                bp[j] = *(const unsigned long long*)&Bs[k][tx * 8 + 2 * j];
            #pragma unroll
            for (int i = 0; i < 8; i++) {
                unsigned long long ad = pk2(a[i], a[i]);
                #pragma unroll
                for (int j = 0; j < 4; j++) fma2(acc[i][j], ad, bp[j]);
            }
        }
        __syncthreads();
    }
    #pragma unroll
    for (int i = 0; i < 8; i++) {
        int m = m0 + ty * 8 + i;
        int n = n0 + tx * 8;
        float o[8];
        #pragma unroll
        for (int j = 0; j < 4; j++) up2(acc[i][j], o[2 * j], o[2 * j + 1]);
        if (EPI == 0) {
            #pragma unroll
            for (int e = 0; e < 8; e++) o[e] = fmaxf(o[e] + bias[n + e], 0.0f);
        } else {
            const float* xp = X + (size_t)m * 256 + n;
            #pragma unroll
            for (int e = 0; e < 8; e++) o[e] = xp[e] + o[e] + bias[n + e];
        }
        float* cp = Cw + (size_t)m * 256 + n;
        *(float4*)(cp)     = make_float4(o[0], o[1], o[2], o[3]);
        *(float4*)(cp + 4) = make_float4(o[4], o[5], o[6], o[7]);
    }
}

// ---------------- 4) LIF over x (transposed view), writes s1[t,c,b] ----------------
__global__ void lif1_kernel(const float* __restrict__ x) {
    int tid = blockIdx.x * blockDim.x + threadIdx.x;
    int c = tid >> 7, b = tid & 127;
    const float4* xr = (const float4*)(x + ((size_t)b * C_ + c) * D_);
    float* sp = g_s1 + (size_t)c * B_ + b;
    float v = 0.0f;
    for (int q = 0; q < 64; q++) {
        float4 xv = xr[q];
        float xa[4] = {xv.x, xv.y, xv.z, xv.w};
        #pragma unroll
        for (int j = 0; j < 4; j++) {
            v = v + (xa[j] - v) * 0.5f;
            float s = (v >= 1.0f) ? 1.0f : 0.0f;
            sp[(size_t)(q * 4 + j) * CB] = s;
            if (v >= 1.0f) v = 0.0f;
        }
    }
}

// ---------------- 5/8) Spike GEMM: Y[t,m,n] = sum_k A[m,k]*S[t,k,n] + bias[m] ----------------
// PH=0: A=cw1 (M=256,K=1024), S=g_s1, Y=g_y1.  PH=1: A=cw2 (M=1024,K=256), S=g_s2, Y=g_y2.
template <int PH>
__global__ void __launch_bounds__(256) gemm_spike(const float* __restrict__ A,
                                                  const float* __restrict__ bias) {
    constexpr int M = (PH == 0) ? 256 : 1024;
    constexpr int K = (PH == 0) ? 1024 : 256;
    const float* S = (PH == 0) ? g_s1 : g_s2;
    float* Y = (PH == 0) ? g_y1 : g_y2;
    __shared__ float As[16][132];
    __shared__ float Bs[16][128];
    int t = blockIdx.y;
    int m0 = blockIdx.x * 128;
    const float* Sb = S + (size_t)t * K * B_;
    int tid = threadIdx.x;
    int tx = tid & 15, ty = tid >> 4;
    unsigned long long acc[8][4] = {};
    int lr = tid >> 2;
    int lk = (tid & 3) << 2;
    int bk = tid >> 4;          // 0..15
    int bn = (tid & 15) << 3;   // 0..120
    for (int k0 = 0; k0 < K; k0 += 16) {
        #pragma unroll
        for (int p = 0; p < 2; p++) {
            float4 av = *(const float4*)(A + (size_t)(m0 + lr + p * 64) * K + k0 + lk);
            As[lk + 0][lr + p * 64] = av.x;
            As[lk + 1][lr + p * 64] = av.y;
            As[lk + 2][lr + p * 64] = av.z;
            As[lk + 3][lr + p * 64] = av.w;
        }
        const float* srow = Sb + (size_t)(k0 + bk) * B_ + bn;
        float4 s0 = *(const float4*)(srow);
        float4 s1v = *(const float4*)(srow + 4);
        *(float4*)&Bs[bk][bn] = s0;
        *(float4*)&Bs[bk][bn + 4] = s1v;
        __syncthreads();
        #pragma unroll
        for (int k = 0; k < 16; k++) {
            float a[8];
            *(float4*)(a)     = *(const float4*)&As[k][ty * 8];
            *(float4*)(a + 4) = *(const float4*)&As[k][ty * 8 + 4];
            unsigned long long bp[4];
            #pragma unroll
            for (int j = 0; j < 4; j++)
                bp[j] = *(const unsigned long long*)&Bs[k][tx * 8 + 2 * j];
            #pragma unroll
            for (int i = 0; i < 8; i++) {
                unsigned long long ad = pk2(a[i], a[i]);
                #pragma unroll
                for (int j = 0; j < 4; j++) fma2(acc[i][j], ad, bp[j]);
            }
        }
        __syncthreads();
    }
    #pragma unroll
    for (int i = 0; i < 8; i++) {
        int m = m0 + ty * 8 + i;
        float bi = bias[m];
        float o[8];
        #pragma unroll
        for (int j = 0; j < 4; j++) up2(acc[i][j], o[2 * j], o[2 * j + 1]);
        #pragma unroll
        for (int e = 0; e < 8; e++) o[e] += bi;
        float* yp = Y + (size_t)t * M * B_ + (size_t)m * B_ + tx * 8;
        *(float4*)(yp)     = make_float4(o[0], o[1], o[2], o[3]);
        *(float4*)(yp + 4) = make_float4(o[4], o[5], o[6], o[7]);
    }
}

// ---------------- 6/9) BatchNorm stats over (t,b) per channel ----------------
template <int PH>
__global__ void bn_stats() {
    constexpr int M = (PH == 0) ? 256 : 1024;
    const float* Y = (PH == 0) ? g_y1 : g_y2;
    float* mu_o = (PH == 0) ? g_mu1 : g_mu2;
    float* rs_o = (PH == 0) ? g_rs1 : g_rs2;
    int m = blockIdx.x;
    const float* yp = Y + (size_t)m * B_;
    float s = 0.0f, q = 0.0f;
    for (int i = threadIdx.x; i < D_ * B_; i += 256) {
        int t = i >> 7, b = i & 127;
        float y = yp[(size_t)t * M * B_ + b];
        s += y;
        q += y * y;
    }
    #pragma unroll
    for (int o = 16; o; o >>= 1) {
        s += __shfl_xor_sync(0xffffffffu, s, o);
        q += __shfl_xor_sync(0xffffffffu, q, o);
    }
    __shared__ float ss[8], qq[8];
    int wid = threadIdx.x >> 5;
    if ((threadIdx.x & 31) == 0) { ss[wid] = s; qq[wid] = q; }
    __syncthreads();
    if (threadIdx.x == 0) {
        float S = 0.0f, Q = 0.0f;
        #pragma unroll
        for (int w = 0; w < 8; w++) { S += ss[w]; Q += qq[w]; }
        float mean = S * (1.0f / (D_ * B_));
        float var = Q * (1.0f / (D_ * B_)) - mean * mean;
        mu_o[m] = mean;
        rs_o[m] = rsqrtf(var + 1e-5f);
    }
}

// ---------------- 7) BN-apply + LIF over y1, writes s2[t,o,b] ----------------
__global__ void lif2_kernel(const float* __restrict__ gam, const float* __restrict__ bet) {
    int tid = blockIdx.x * blockDim.x + threadIdx.x;   // 32768
    int m = tid >> 7, b = tid & 127;
    float mu = g_mu1[m], rs = g_rs1[m], ga = gam[m], be = bet[m];
    const float* yp = g_y1 + (size_t)m * B_ + b;
    float* sp = g_s2 + (size_t)m * B_ + b;
    float v = 0.0f;
    for (int t = 0; t < D_; t++) {
        float y = yp[(size_t)t * OB];
        float yn = ((y - mu) * rs) * ga + be;
        v = v + (yn - v) * 0.5f;
        float s = (v >= 1.0f) ? 1.0f : 0.0f;
        sp[(size_t)t * OB] = s;
        if (v >= 1.0f) v = 0.0f;
    }
}

// ---------------- 10) BN2-apply + transpose + accumulate into out ----------------
__global__ void final_kernel(float* __restrict__ out, const float* __restrict__ gam,
                             const float* __restrict__ bet) {
    __shared__ float tile[32][33];
    int c = blockIdx.x;
    int t0 = blockIdx.y << 5;
    int b0 = blockIdx.z << 5;
    float mu = g_mu2[c], rs = g_rs2[c], ga = gam[c], be = bet[c];
    #pragma unroll
    for (int r = 0; r < 4; r++) {
        int t = t0 + threadIdx.y + r * 8;
        float y = g_y2[(size_t)t * CB + (size_t)c * B_ + b0 + threadIdx.x];
        tile[threadIdx.y + r * 8][threadIdx.x] = ((y - mu) * rs) * ga + be;
    }
    __syncthreads();
    #pragma unroll
    for (int r = 0; r < 4; r++) {
        int b = b0 + threadIdx.y + r * 8;
        size_t o = (size_t)b * (C_ * D_) + (size_t)c * D_ + t0 + threadIdx.x;
        out[o] += tile[threadIdx.x][threadIdx.y + r * 8];
    }
}

// ---------------- launch ----------------
extern "C" void kernel_launch(void* const* d_in, const int* in_sizes, int n_in,
                              void* d_out, int out_size) {
    const float* x    = (const float*)d_in[0];
    const float* ln_g = (const float*)d_in[1];
    const float* ln_b = (const float*)d_in[2];
    const float* w1   = (const float*)d_in[3];
    const float* b1   = (const float*)d_in[4];
    const float* w2   = (const float*)d_in[5];
    const float* b2   = (const float*)d_in[6];
    const float* cw1  = (const float*)d_in[7];
    const float* cb1  = (const float*)d_in[8];
    const float* bn1g = (const float*)d_in[9];
    const float* bn1b = (const float*)d_in[10];
    const float* cw2  = (const float*)d_in[11];
    const float* cb2  = (const float*)d_in[12];
    const float* bn2g = (const float*)d_in[13];
    const float* bn2b = (const float*)d_in[14];
    float* out = (float*)d_out;

    (void)in_sizes; (void)n_in; (void)out_size;

    // Mix branch (writes x1 into out)
    ln_kernel<<<ROWS / 8, 256>>>(x, ln_g, ln_b);
    gemm_mix<0><<<dim3(ROWS / 128, 2), 256>>>(w1, b1, nullptr, nullptr);
    gemm_mix<1><<<dim3(ROWS / 128, 2), 256>>>(w2, b2, x, out);

    // Spiking branch
    lif1_kernel<<<CB / 256, 256>>>(x);
    gemm_spike<0><<<dim3(2, D_), 256>>>(cw1, cb1);
    bn_stats<0><<<256, 256>>>();
    lif2_kernel<<<OB / 256, 256>>>(bn1g, bn1b);
    gemm_spike<1><<<dim3(8, D_), 256>>>(cw2, cb2);
    bn_stats<1><<<1024, 256>>>();
    final_kernel<<<dim3(C_, D_ / 32, B_ / 32), dim3(32, 8)>>>(out, bn2g, bn2b);
}